// round 11
// baseline (speedup 1.0000x reference)
#include <cuda_runtime.h>
#include <cstdint>

#define NC 256
#define NH 256
#define NW 256
#define NBOX 100
#define GRID 1184                 // 148 SMs x 8 blocks: exactly one wave, co-resident
#define CHUNKS (NC * 64)          // 16384 chunks of 256 float4 (64 chunks per channel)

__device__ float4   g_coef[NC];        // A, B1, B2, D per channel
__device__ unsigned g_arrive = 0;      // grid barrier (self-resetting)
__device__ unsigned g_depart = 0;

// ---------------------------------------------------------------------------
// One kernel. Blocks 0..255 compute per-channel coefficients; all 1184 blocks
// cross a software grid barrier (safe: whole grid is one resident wave), then
// stream the 67MB output at the L2 write cap.
//   out[c,h,w] = w*(w*A - B1) + h*(h*A - B2) + D
// nonzero(size=100, fill=0) == each selected box once + (100-cnt) copies of box 0.
// ---------------------------------------------------------------------------
__global__ __launch_bounds__(256, 8)
void fused_kernel(const float* __restrict__ boxes,
                  const float* __restrict__ scores,
                  const float* __restrict__ feat,
                  float4* __restrict__ out) {
    __shared__ float4 red[128];
    __shared__ int    s_pc[8];
    const int tid = threadIdx.x;
    const int bid = blockIdx.x;

    // ================= Phase 1: coef (blocks 0..255 only) =================
    if (bid < NC) {
        const int c = bid;
        int m = 0;
        if (tid < NBOX) m = (scores[tid] > 0.0f) ? 1 : 0;
        unsigned bal = __ballot_sync(0xffffffffu, m);
        if ((tid & 31) == 0) s_pc[tid >> 5] = __popc(bal);
        __syncthreads();
        const int cnt = s_pc[0] + s_pc[1] + s_pc[2] + s_pc[3];  // warps 4-7 contribute 0

        float4 acc = make_float4(0.f, 0.f, 0.f, 0.f);
        if (tid < NBOX) {
            const float4* b4 = (const float4*)(boxes + (size_t)tid * 24);
            float4 v0 = b4[0], v1 = b4[1], v2 = b4[2], v3 = b4[3], v4 = b4[4], v5 = b4[5];
            // corners are (x,y,z) triples: x at 0,3,..,21 ; y at 1,4,..,22
            float xs[8] = {v0.x, v0.w, v1.z, v2.y, v3.x, v3.w, v4.z, v5.y};
            float ys[8] = {v0.y, v1.x, v1.w, v2.z, v3.y, v4.x, v4.w, v5.z};
            float lx = xs[0], rx = xs[0], ly = ys[0], ry = ys[0];
            #pragma unroll
            for (int k = 1; k < 8; k++) {
                lx = fminf(lx, xs[k]); rx = fmaxf(rx, xs[k]);
                ly = fminf(ly, ys[k]); ry = fmaxf(ry, ys[k]);
            }
            float cx  = ((lx + rx) * 0.5f + 128.0f) / 160.0f;
            float cy  = ((ly + ry) * 0.5f + 128.0f) / 160.0f;
            float bev = ((ry - ly) / 160.0f) * ((rx - lx) / 160.0f);
            float a   = 1.0f / (2.0f * bev * bev);
            float r2  = cx * cx + cy * cy;

            // bilinear grid_sample (zero pad, align_corners=False)
            float ix = ((cx + 1.0f) * (float)NW - 1.0f) * 0.5f;
            float iy = ((cy + 1.0f) * (float)NH - 1.0f) * 0.5f;
            float x0f = floorf(ix), y0f = floorf(iy);
            float wx1 = ix - x0f, wx0 = 1.0f - wx1;
            float wy1 = iy - y0f, wy0 = 1.0f - wy1;
            int x0 = (int)x0f, y0 = (int)y0f, x1 = x0 + 1, y1 = y0 + 1;
            bool vx0 = (x0 >= 0 && x0 < NW), vx1 = (x1 >= 0 && x1 < NW);
            bool vy0 = (y0 >= 0 && y0 < NH), vy1 = (y1 >= 0 && y1 < NH);
            int px0 = min(max(x0, 0), NW - 1), px1 = min(max(x1, 0), NW - 1);
            int py0 = min(max(y0, 0), NH - 1), py1 = min(max(y1, 0), NH - 1);
            float w00 = (vx0 && vy0) ? wx0 * wy0 : 0.0f;
            float w10 = (vx1 && vy0) ? wx1 * wy0 : 0.0f;
            float w01 = (vx0 && vy1) ? wx0 * wy1 : 0.0f;
            float w11 = (vx1 && vy1) ? wx1 * wy1 : 0.0f;

            const float* fc = feat + (size_t)c * NH * NW;
            float v = w00 * __ldg(fc + py0 * NW + px0)
                    + w10 * __ldg(fc + py0 * NW + px1)
                    + w01 * __ldg(fc + py1 * NW + px0)
                    + w11 * __ldg(fc + py1 * NW + px1);

            float mult = (tid == 0) ? (float)(m + NBOX - cnt) : (float)m;
            float ta = v * a * mult;
            acc = make_float4(ta, ta * cx, ta * cy, ta * r2);
        }
        if (tid < 128) red[tid] = acc;
        __syncthreads();
        // Safe tree reduction (cross-warp deps -> __syncthreads every step)
        #pragma unroll
        for (int s = 64; s > 0; s >>= 1) {
            if (tid < s) {
                float4 u = red[tid], v = red[tid + s];
                red[tid] = make_float4(u.x + v.x, u.y + v.y, u.z + v.z, u.w + v.w);
            }
            __syncthreads();
        }
        if (tid == 0) {
            const float inv = 1.0f / (float)NBOX;
            float4 r = red[0];
            g_coef[c] = make_float4(r.x * inv, 2.0f * r.y * inv, 2.0f * r.z * inv, r.w * inv);
        }
    }
    __syncthreads();

    // ================= Grid barrier (self-resetting) =================
    if (tid == 0) {
        __threadfence();                                  // coef visible before arrive
        atomicAdd(&g_arrive, 1u);
        while (*(volatile unsigned*)&g_arrive < GRID) __nanosleep(64);
        __threadfence();                                  // acquire coefs
        unsigned d = atomicAdd(&g_depart, 1u) + 1u;
        if (d == GRID) {                                  // last out resets for next call
            g_arrive = 0u;
            __threadfence();
            g_depart = 0u;
        }
    }
    __syncthreads();

    // ================= Phase 2: streaming writer (all blocks) =================
    // chunk k covers float4 indices [ (k&63)*256 , +256 ) of channel k>>6.
    for (int k = bid; k < CHUNKS; k += GRID) {
        const int c = k >> 6;
        const float4 k4 = __ldg(&g_coef[c]);
        const float A = k4.x, B1 = k4.y, B2 = k4.z, D = k4.w;

        int   il   = ((k & 63) << 8) + tid;       // float4 index within channel
        float hf   = (float)(il >> 6);
        float w0   = (float)((il & 63) * 4);
        float base = fmaf(hf, fmaf(hf, A, -B2), D);
        float r0 = fmaf(w0,       fmaf(w0,       A, -B1), base);
        float r1 = fmaf(w0 + 1.f, fmaf(w0 + 1.f, A, -B1), base);
        float r2 = fmaf(w0 + 2.f, fmaf(w0 + 2.f, A, -B1), base);
        float r3 = fmaf(w0 + 3.f, fmaf(w0 + 3.f, A, -B1), base);
        out[(size_t)c * (NH * NW / 4) + il] = make_float4(r0, r1, r2, r3);
    }
}

// ---------------------------------------------------------------------------
extern "C" void kernel_launch(void* const* d_in, const int* in_sizes, int n_in,
                              void* d_out, int out_size) {
    const float* boxes  = (const float*)d_in[0];   // [100,8,3]
    const float* scores = (const float*)d_in[1];   // [100]
    const float* feat   = (const float*)d_in[2];   // [1,256,256,256]

    fused_kernel<<<GRID, 256>>>(boxes, scores, feat, (float4*)d_out);
    (void)in_sizes; (void)n_in; (void)out_size;
}

// round 12
// speedup vs baseline: 1.2330x; 1.2330x over previous
#include <cuda_runtime.h>
#include <cstdint>

#define NC 256
#define NH 256
#define NW 256
#define NBOX 100
#define SLICES 8                       // writer blocks per channel (best measured)
#define ROWS_PER_SLICE (NH / SLICES)   // 32
#define TILE_F4 (ROWS_PER_SLICE * NW / 4)   // 2048 float4 per block

// Per-box precomputed params (channel-independent)
__device__ float4 g_pw[NBOX];   // bilinear weights w00,w10,w01,w11 (zeroed if OOB)
__device__ int4   g_po[NBOX];   // 4 gather offsets into a channel plane
__device__ float4 g_pk[NBOX];   // (a*mult/N, 2*cx, 2*cy, cx^2+cy^2)

// ---------------------------------------------------------------------------
// Kernel 1 (tiny): per-box geometry + grid_sample weights/offsets.
// nonzero(size=100, fill=0) == each selected box once + (100-cnt) copies of box 0.
// ---------------------------------------------------------------------------
__global__ __launch_bounds__(128)
void box_kernel(const float* __restrict__ boxes,
                const float* __restrict__ scores) {
    __shared__ int s_pc[4];
    const int tid = threadIdx.x;

    int m = 0;
    if (tid < NBOX) m = (scores[tid] > 0.0f) ? 1 : 0;
    unsigned bal = __ballot_sync(0xffffffffu, m);
    if ((tid & 31) == 0) s_pc[tid >> 5] = __popc(bal);
    __syncthreads();
    const int cnt = s_pc[0] + s_pc[1] + s_pc[2] + s_pc[3];

    if (tid < NBOX) {
        const float4* b4 = (const float4*)(boxes + (size_t)tid * 24);
        float4 v0 = b4[0], v1 = b4[1], v2 = b4[2], v3 = b4[3], v4 = b4[4], v5 = b4[5];
        // corners are (x,y,z) triples: x at 0,3,..,21 ; y at 1,4,..,22
        float xs[8] = {v0.x, v0.w, v1.z, v2.y, v3.x, v3.w, v4.z, v5.y};
        float ys[8] = {v0.y, v1.x, v1.w, v2.z, v3.y, v4.x, v4.w, v5.z};
        float lx = xs[0], rx = xs[0], ly = ys[0], ry = ys[0];
        #pragma unroll
        for (int k = 1; k < 8; k++) {
            lx = fminf(lx, xs[k]); rx = fmaxf(rx, xs[k]);
            ly = fminf(ly, ys[k]); ry = fmaxf(ry, ys[k]);
        }
        float cx  = ((lx + rx) * 0.5f + 128.0f) / 160.0f;
        float cy  = ((ly + ry) * 0.5f + 128.0f) / 160.0f;
        float bev = ((ry - ly) / 160.0f) * ((rx - lx) / 160.0f);
        float a   = 1.0f / (2.0f * bev * bev);

        // bilinear grid_sample (zero pad, align_corners=False)
        float ix = ((cx + 1.0f) * (float)NW - 1.0f) * 0.5f;
        float iy = ((cy + 1.0f) * (float)NH - 1.0f) * 0.5f;
        float x0f = floorf(ix), y0f = floorf(iy);
        float wx1 = ix - x0f, wx0 = 1.0f - wx1;
        float wy1 = iy - y0f, wy0 = 1.0f - wy1;
        int x0 = (int)x0f, y0 = (int)y0f, x1 = x0 + 1, y1 = y0 + 1;
        bool vx0 = (x0 >= 0 && x0 < NW), vx1 = (x1 >= 0 && x1 < NW);
        bool vy0 = (y0 >= 0 && y0 < NH), vy1 = (y1 >= 0 && y1 < NH);
        int px0 = min(max(x0, 0), NW - 1), px1 = min(max(x1, 0), NW - 1);
        int py0 = min(max(y0, 0), NH - 1), py1 = min(max(y1, 0), NH - 1);

        g_pw[tid] = make_float4((vx0 && vy0) ? wx0 * wy0 : 0.0f,
                                (vx1 && vy0) ? wx1 * wy0 : 0.0f,
                                (vx0 && vy1) ? wx0 * wy1 : 0.0f,
                                (vx1 && vy1) ? wx1 * wy1 : 0.0f);
        g_po[tid] = make_int4(py0 * NW + px0, py0 * NW + px1,
                              py1 * NW + px0, py1 * NW + px1);

        float mult = (tid == 0) ? (float)(m + NBOX - cnt) : (float)m;
        // fold mult, 1/N, and the factors of 2 so the reduce yields (A,B1,B2,D)
        g_pk[tid] = make_float4(a * mult * (1.0f / (float)NBOX),
                                2.0f * cx, 2.0f * cy, cx * cx + cy * cy);
    }
    __syncthreads();
    if (tid == 0) __threadfence();
    __syncthreads();
    asm volatile("griddepcontrol.launch_dependents;");
}

// ---------------------------------------------------------------------------
// Kernel 2: per-block coef gather+reduce (cheap), then streaming STG.128 writer.
//   out[c,h,w] = w*(w*A - B1) + h*(h*A - B2) + D
// ---------------------------------------------------------------------------
__global__ __launch_bounds__(256)
void out_kernel(const float* __restrict__ feat, float4* __restrict__ out) {
    __shared__ float4 red[128];
    asm volatile("griddepcontrol.wait;" ::: "memory");
    const int tid   = threadIdx.x;
    const int c     = blockIdx.x >> 3;
    const int slice = blockIdx.x & 7;

    // ---- prologue: 100 gathers + tree reduce -> (A, B1, B2, D) ----
    float4 acc = make_float4(0.f, 0.f, 0.f, 0.f);
    if (tid < NBOX) {
        float4 wv = g_pw[tid];
        int4   ov = g_po[tid];
        float4 kv = g_pk[tid];
        const float* fc = feat + (size_t)c * NH * NW;
        float v = wv.x * __ldg(fc + ov.x) + wv.y * __ldg(fc + ov.y)
                + wv.z * __ldg(fc + ov.z) + wv.w * __ldg(fc + ov.w);
        float ta = v * kv.x;
        acc = make_float4(ta, ta * kv.y, ta * kv.z, ta * kv.w);
    }
    if (tid < 128) red[tid] = acc;
    __syncthreads();
    #pragma unroll
    for (int s = 64; s > 0; s >>= 1) {
        if (tid < s) {
            float4 u = red[tid], v = red[tid + s];
            red[tid] = make_float4(u.x + v.x, u.y + v.y, u.z + v.z, u.w + v.w);
        }
        __syncthreads();
    }
    const float A  = red[0].x;
    const float B1 = red[0].y;
    const float B2 = red[0].z;
    const float D  = red[0].w;

    // ---- streaming writer: 8 STG.128 per thread (L2 write-cap path) ----
    float4* oc = out + (size_t)blockIdx.x * TILE_F4;
    const float w0 = (float)((tid & 63) * 4);
    const float pw0 = (w0      ) * fmaf(w0,       A, -B1);
    const float pw1 = (w0 + 1.f) * fmaf(w0 + 1.f, A, -B1);
    const float pw2 = (w0 + 2.f) * fmaf(w0 + 2.f, A, -B1);
    const float pw3 = (w0 + 3.f) * fmaf(w0 + 3.f, A, -B1);

    #pragma unroll
    for (int k = 0; k < TILE_F4 / 256; k++) {   // 8 iters
        int   i    = k * 256 + tid;
        float hf   = (float)(slice * ROWS_PER_SLICE + (i >> 6));
        float base = fmaf(hf, fmaf(hf, A, -B2), D);
        oc[i] = make_float4(pw0 + base, pw1 + base, pw2 + base, pw3 + base);
    }
}

// ---------------------------------------------------------------------------
extern "C" void kernel_launch(void* const* d_in, const int* in_sizes, int n_in,
                              void* d_out, int out_size) {
    const float* boxes  = (const float*)d_in[0];   // [100,8,3]
    const float* scores = (const float*)d_in[1];   // [100]
    const float* feat   = (const float*)d_in[2];   // [1,256,256,256]

    box_kernel<<<1, 128>>>(boxes, scores);

    cudaLaunchConfig_t cfg = {};
    cfg.gridDim  = dim3(NC * SLICES);   // 2048 blocks
    cfg.blockDim = dim3(256);
    cfg.dynamicSmemBytes = 0;
    cfg.stream = 0;
    cudaLaunchAttribute attr[1];
    attr[0].id = cudaLaunchAttributeProgrammaticStreamSerialization;
    attr[0].val.programmaticStreamSerializationAllowed = 1;
    cfg.attrs = attr;
    cfg.numAttrs = 1;
    cudaLaunchKernelEx(&cfg, out_kernel, feat, (float4*)d_out);

    (void)in_sizes; (void)n_in; (void)out_size;
}